// round 7
// baseline (speedup 1.0000x reference)
#include <cuda_runtime.h>
#include <cstdint>

// out[N,N] = diag(ics_mask - params * r_mask), N = 12288. Pure store-bound (604 MB).
// R6 change: 64 B per thread (4x float4, front-batched) + __stcs streaming stores
// (write-once buffer; evict-first avoids L2 write-allocate churn).

static constexpr unsigned N   = 12288u;
static constexpr unsigned N16 = (N * N) / 16u;   // 9,437,184 threads, 16 floats each

__global__ void __launch_bounds__(256) diag_fill_kernel(
    float4* __restrict__ out4,
    const float* __restrict__ params,
    const int*   __restrict__ r_mask,
    const int*   __restrict__ ics_mask)
{
    unsigned t = blockIdx.x * blockDim.x + threadIdx.x;   // < N16 exactly
    unsigned j = t * 16u;                                  // first element index

    float vals[16];
    #pragma unroll
    for (int k = 0; k < 16; ++k) vals[k] = 0.0f;

    // Diagonal indices are d = i*(N+1). N+1 = 12289 > 16, so at most one
    // diagonal element lands in [j, j+16).
    unsigned i = (j + N) / (N + 1u);          // ceil(j/(N+1)) -> mul+shift
    unsigned d = i * (N + 1u);
    if (i < N && d < j + 16u) {
        float val = (float)ics_mask[i] - params[i] * (float)r_mask[i];
        vals[d - j] = val;
    }

    float4* p = out4 + t * 4u;
    #pragma unroll
    for (int k = 0; k < 4; ++k) {
        float4 v = make_float4(vals[4*k + 0], vals[4*k + 1],
                               vals[4*k + 2], vals[4*k + 3]);
        __stcs(p + k, v);                     // st.global.cs.v4 (evict-first)
    }
}

extern "C" void kernel_launch(void* const* d_in, const int* in_sizes, int n_in,
                              void* d_out, int out_size)
{
    const float* params   = (const float*)d_in[0];
    const int*   r_mask   = (const int*)  d_in[1];
    const int*   ics_mask = (const int*)  d_in[2];
    float4*      out4     = (float4*)d_out;

    (void)in_sizes; (void)n_in; (void)out_size;

    const unsigned threads = 256;
    const unsigned blocks  = N16 / threads;   // 36,864 — exact, no tail
    diag_fill_kernel<<<blocks, threads>>>(out4, params, r_mask, ics_mask);
}

// round 8
// speedup vs baseline: 1.7629x; 1.7629x over previous
#include <cuda_runtime.h>
#include <cstdint>

// out[N,N] = diag(ics_mask - params * r_mask), N = 12288. Pure store-bound (604 MB).
// R7 fix: R6 broke intra-warp coalescing (consecutive float4s per thread -> 64B
// lane stride -> partial-sector writes, DRAM 83%->48%). Now block-strided
// batching: 4 float4 stores per thread, each warp instruction covers a
// contiguous 512 B run. Keep __stcs (write-once buffer, evict-first).

static constexpr unsigned N  = 12288u;
static constexpr unsigned N4 = (N * N) / 4u;   // 37,748,736 float4 stores

__global__ void __launch_bounds__(256) diag_fill_kernel(
    float4* __restrict__ out4,
    const float* __restrict__ params,
    const int*   __restrict__ r_mask,
    const int*   __restrict__ ics_mask)
{
    // Block owns 4*256 = 1024 consecutive float4s. Chunk c: index base + c*256 + tid.
    unsigned base = blockIdx.x * 1024u + threadIdx.x;

    #pragma unroll
    for (unsigned c = 0; c < 4u; ++c) {
        unsigned f = base + c * 256u;          // float4 index, < N4 exactly
        unsigned j = f * 4u;                   // first element index of this window

        float4 v = make_float4(0.f, 0.f, 0.f, 0.f);

        // Diagonal indices d = i*(N+1); N+1 = 12289 > 4 -> at most one hit per window.
        unsigned i = (j + N) / (N + 1u);       // ceil(j/(N+1)) -> mul+shift
        unsigned d = i * (N + 1u);
        if (i < N && d < j + 4u) {
            float val = (float)ics_mask[i] - params[i] * (float)r_mask[i];
            unsigned off = d - j;
            if      (off == 0u) v.x = val;
            else if (off == 1u) v.y = val;
            else if (off == 2u) v.z = val;
            else                v.w = val;
        }

        __stcs(out4 + f, v);                   // st.global.cs.v4, coalesced
    }
}

extern "C" void kernel_launch(void* const* d_in, const int* in_sizes, int n_in,
                              void* d_out, int out_size)
{
    const float* params   = (const float*)d_in[0];
    const int*   r_mask   = (const int*)  d_in[1];
    const int*   ics_mask = (const int*)  d_in[2];
    float4*      out4     = (float4*)d_out;

    (void)in_sizes; (void)n_in; (void)out_size;

    const unsigned threads = 256;
    const unsigned blocks  = N4 / (threads * 4u);   // 36,864 — exact, no tail
    diag_fill_kernel<<<blocks, threads>>>(out4, params, r_mask, ics_mask);
}